// round 14
// baseline (speedup 1.0000x reference)
#include <cuda_runtime.h>
#include <cuda_fp16.h>
#include <math.h>
#include <stdint.h>

// ---------------- problem constants ----------------
#define BB   8
#define LL   8192
#define CC   256
#define PEC  96
#define RR   90
#define UP   4
#define OUTC 256
#define KK   448
#define NN   1024
#define MM   (BB * LL)       // 65536

#define FC_GAIN      0.04724555912615336f   // 1/sqrt(448)
#define SQRT2_F      1.4142135623730951f
#define INV_SQRT2_F  0.7071067811865476f
#define INV_SQRT3_F  0.5773502691896258f

// ---------------- tiling ----------------
#define NCHUNK  14          // K chunks of 32
#define MTILES  512         // M/128
#define NBLKS   8           // N/128
__device__ uint4 g_Afrag[(size_t)MTILES * NCHUNK * 512];   // ~59 MB
__device__ uint4 g_Bfrag[(size_t)NBLKS * NCHUNK * 512];    // ~0.9 MB
__device__ float g_cpeT[3 * RR * PEC];                     // transposed const_pe

__device__ __forceinline__ uint32_t pkh2(float a, float b) {
    __half2 h = __floats2half2_rn(a, b);
    return *reinterpret_cast<uint32_t*>(&h);
}
__device__ __forceinline__ uint32_t smem_u32(const void* p) {
    uint32_t a;
    asm("{ .reg .u64 t; cvta.to.shared.u64 t, %1; cvt.u32.u64 %0, t; }" : "=r"(a) : "l"(p));
    return a;
}
__device__ __forceinline__ void cp16(uint32_t dst, const void* src) {
    asm volatile("cp.async.cg.shared.global [%0], [%1], 16;" :: "r"(dst), "l"(src) : "memory");
}
__device__ __forceinline__ void cp_commit() { asm volatile("cp.async.commit_group;" ::: "memory"); }
__device__ __forceinline__ void cp_wait1()  { asm volatile("cp.async.wait_group 1;" ::: "memory"); }
__device__ __forceinline__ void cp_wait0()  { asm volatile("cp.async.wait_group 0;" ::: "memory"); }

// ---------------------------------------------------------------------------
// prep 0: transpose const_pe [3][96][90] -> g_cpeT [3][90][96]
// ---------------------------------------------------------------------------
__global__ __launch_bounds__(256) void t_prep(const float* __restrict__ cpe_tab)
{
    int i = blockIdx.x * 256 + threadIdx.x;
    if (i < 3 * RR * PEC) {
        int d  = i % PEC;
        int r  = (i / PEC) % RR;
        int ch = i / (PEC * RR);
        g_cpeT[i] = cpe_tab[((size_t)ch * PEC + d) * RR + r];
    }
}

// ---------------------------------------------------------------------------
// prep 1: PE columns (fragments for chunks 8..13) + pc_up.
// ---------------------------------------------------------------------------
__global__ __launch_bounds__(128) void pe_prep(
    const float* __restrict__ pc,
    const float* __restrict__ lff_w,
    const float* __restrict__ lff_b,
    float* __restrict__ out_pc)
{
    __shared__ float spe[16][192];
    const int t   = threadIdx.x;
    const int m0  = blockIdx.x * 16;
    const int row = t & 15;
    const int dsl = t >> 4;              // 0..7
    const int gm  = m0 + row;

    const float p0 = pc[gm * 3 + 0];
    const float p1 = pc[gm * 3 + 1];
    const float p2 = pc[gm * 3 + 2];
    const float pcv[3] = {p0, p1, p2};

    int   idx0[3], idx1[3];
    float w0[3], w1[3];
    #pragma unroll
    for (int ch = 0; ch < 3; ch++) {
        float ix  = ((pcv[ch] + 1.0f) * (float)RR - 1.0f) * 0.5f;
        float fi0 = floorf(ix);
        float w   = ix - fi0;
        int   i0  = (int)fi0;
        int   i1  = i0 + 1;
        bool  v0  = (i0 >= 0 && i0 < RR);
        bool  v1  = (i1 >= 0 && i1 < RR);
        idx0[ch] = v0 ? i0 : 0;
        idx1[ch] = v1 ? i1 : 0;
        w0[ch] = v0 ? (1.0f - w) * INV_SQRT3_F : 0.0f;
        w1[ch] = v1 ? w * INV_SQRT3_F : 0.0f;
    }

    #pragma unroll
    for (int c4 = 0; c4 < 3; c4++) {
        const int d0 = dsl * 12 + c4 * 4;      // 0..92 step 4

        float4 wa = *reinterpret_cast<const float4*>(lff_w + d0 * 3);
        float4 wb = *reinterpret_cast<const float4*>(lff_w + d0 * 3 + 4);
        float4 wc = *reinterpret_cast<const float4*>(lff_w + d0 * 3 + 8);
        float4 bb = *reinterpret_cast<const float4*>(lff_b + d0);
        spe[row][d0 + 0] = __sinf(fmaf(p0, wa.x, fmaf(p1, wa.y, fmaf(p2, wa.z, bb.x))));
        spe[row][d0 + 1] = __sinf(fmaf(p0, wa.w, fmaf(p1, wb.x, fmaf(p2, wb.y, bb.y))));
        spe[row][d0 + 2] = __sinf(fmaf(p0, wb.z, fmaf(p1, wb.w, fmaf(p2, wc.x, bb.z))));
        spe[row][d0 + 3] = __sinf(fmaf(p0, wc.y, fmaf(p1, wc.z, fmaf(p2, wc.w, bb.w))));

        float4 acc = make_float4(0.f, 0.f, 0.f, 0.f);
        #pragma unroll
        for (int ch = 0; ch < 3; ch++) {
            const float* base = g_cpeT + (size_t)ch * RR * PEC;
            float4 v0 = *reinterpret_cast<const float4*>(base + idx0[ch] * PEC + d0);
            float4 v1 = *reinterpret_cast<const float4*>(base + idx1[ch] * PEC + d0);
            acc.x = fmaf(v0.x, w0[ch], fmaf(v1.x, w1[ch], acc.x));
            acc.y = fmaf(v0.y, w0[ch], fmaf(v1.y, w1[ch], acc.y));
            acc.z = fmaf(v0.z, w0[ch], fmaf(v1.z, w1[ch], acc.z));
            acc.w = fmaf(v0.w, w0[ch], fmaf(v1.w, w1[ch], acc.w));
        }
        *reinterpret_cast<float4*>(&spe[row][PEC + d0]) = acc;
    }

    if (dsl < 6) {
        #pragma unroll
        for (int q = 0; q < 2; q++) {
            int it = dsl * 2 + q;
            int u = it / 3;
            int k = it - u * 3;
            float v = (k == 0) ? p0 : (k == 1) ? p1 : p2;
            out_pc[((size_t)gm * UP + u) * 3 + k] = v;
        }
    }
    __syncthreads();

    const int mt  = m0 >> 7;
    const int m16 = (m0 & 127) >> 4;
    #pragma unroll
    for (int j = 0; j < 3; j++) {
        const int fid  = j * 128 + t;    // 0..383
        const int lane = fid & 31;
        const int ks   = (fid >> 5) & 1;
        const int ch   = fid >> 6;       // 0..5
        const int grp  = lane >> 2;
        const int qid  = lane & 3;
        const int c0   = ch * 32 + ks * 16 + 2 * qid;
        uint4 o;
        o.x = pkh2(spe[grp][c0],     spe[grp][c0 + 1]);
        o.y = pkh2(spe[grp + 8][c0], spe[grp + 8][c0 + 1]);
        o.z = pkh2(spe[grp][c0 + 8], spe[grp][c0 + 9]);
        o.w = pkh2(spe[grp + 8][c0 + 8], spe[grp + 8][c0 + 9]);
        const int chunk = 8 + ch;
        g_Afrag[((size_t)mt * NCHUNK + chunk) * 512 + (m16 * 2 + ks) * 32 + lane] = o;
    }
}

// ---------------------------------------------------------------------------
// prep 2: x -> fragments for chunks 0..7.
// ---------------------------------------------------------------------------
__global__ __launch_bounds__(128) void a_prep(const float* __restrict__ x)
{
    __shared__ float s[128][36];
    const int t     = threadIdx.x;
    const int chunk = blockIdx.x;        // 0..7
    const int mt    = blockIdx.y;        // 0..511
    const int m0    = mt * 128;
    const int k0    = chunk * 32;

    #pragma unroll
    for (int j = 0; j < 8; j++) {
        const int id  = j * 128 + t;
        const int row = id >> 3;
        const int c4  = (id & 7) * 4;
        float4 v = *reinterpret_cast<const float4*>(
            x + (size_t)(m0 + row) * CC + k0 + c4);
        *reinterpret_cast<float4*>(&s[row][c4]) = v;
    }
    __syncthreads();

    #pragma unroll
    for (int j = 0; j < 4; j++) {
        const int fid  = j * 128 + t;
        const int lane = fid & 31;
        const int ks   = (fid >> 5) & 1;
        const int m16  = fid >> 6;
        const int grp  = lane >> 2;
        const int qid  = lane & 3;
        const int r0   = m16 * 16 + grp;
        const int c0   = ks * 16 + 2 * qid;
        uint4 o;
        o.x = pkh2(s[r0][c0],     s[r0][c0 + 1]);
        o.y = pkh2(s[r0 + 8][c0], s[r0 + 8][c0 + 1]);
        o.z = pkh2(s[r0][c0 + 8], s[r0][c0 + 9]);
        o.w = pkh2(s[r0 + 8][c0 + 8], s[r0 + 8][c0 + 9]);
        g_Afrag[((size_t)mt * NCHUNK + chunk) * 512 + fid] = o;
    }
}

// ---------------------------------------------------------------------------
// prep 3: sub_w -> B fragments.
// ---------------------------------------------------------------------------
__global__ __launch_bounds__(128) void b_prep(const float* __restrict__ sub_w)
{
    const int t     = threadIdx.x;
    const int chunk = blockIdx.x;        // 0..13
    const int nb    = blockIdx.y;        // 0..7
    uint2* dst = reinterpret_cast<uint2*>(g_Bfrag + ((size_t)nb * NCHUNK + chunk) * 512);

    #pragma unroll
    for (int j = 0; j < 8; j++) {
        const int fid  = j * 128 + t;
        const int lane = fid & 31;
        const int ks   = (fid >> 5) & 1;
        const int n8   = fid >> 6;
        const int grp  = lane >> 2;
        const int qid  = lane & 3;
        const int n    = nb * 128 + n8 * 8 + grp;
        const int k    = chunk * 32 + ks * 16 + 2 * qid;
        float2 v01 = *reinterpret_cast<const float2*>(sub_w + (size_t)n * KK + k);
        float2 v23 = *reinterpret_cast<const float2*>(sub_w + (size_t)n * KK + k + 8);
        uint2 o;
        o.x = pkh2(v01.x, v01.y);
        o.y = pkh2(v23.x, v23.y);
        dst[fid] = o;
    }
}

// ---------------------------------------------------------------------------
// GEMM: fp16 mma.sync m16n8k16, CTA 128x128, BK=32, 3-stage cp.async pipeline
// with prefetch distance 2 (round-4-proven pattern; NO stage aliasing).
// 4 warps (128 threads), warp tile 64x64: wm = wid>>1, wn = wid&1.
// ---------------------------------------------------------------------------
__global__ __launch_bounds__(128) void gemm_hmma(
    const float* __restrict__ x,
    const float* __restrict__ sub_b,
    float* __restrict__ out_xup)
{
    __shared__ __align__(16) char smem[49152];   // 3 stages x (A 8KB + B 8KB)
    const uint32_t sb = smem_u32(smem);

    const int tid  = threadIdx.x;
    const int wid  = tid >> 5;
    const int lane = tid & 31;
    const int grp  = lane >> 2;
    const int qid  = lane & 3;
    const int wm   = wid >> 1;       // 0..1 -> 64-row slab
    const int wn   = wid & 1;        // 0..1 -> 64-col slab
    const int nb   = blockIdx.x;     // 0..7
    const int mt   = blockIdx.y;     // 0..511

    const char* gA = (const char*)(g_Afrag + (size_t)mt * NCHUNK * 512);
    const char* gB = (const char*)(g_Bfrag + (size_t)nb * NCHUNK * 512);

    float acc[4][8][4];
    #pragma unroll
    for (int i = 0; i < 4; i++)
        #pragma unroll
        for (int j = 0; j < 8; j++)
            #pragma unroll
            for (int q = 0; q < 4; q++) acc[i][j][q] = 0.0f;

    // 16KB per chunk, 128 threads -> 8 cp16 each
    #define ISSUE(c, s) do { \
        const char* a_ = gA + (size_t)(c) * 8192; \
        const char* b_ = gB + (size_t)(c) * 8192; \
        uint32_t dA = sb + (s) * 16384; \
        uint32_t dB = dA + 8192; \
        cp16(dA + tid * 16,         a_ + tid * 16); \
        cp16(dA + (tid + 128) * 16, a_ + (tid + 128) * 16); \
        cp16(dA + (tid + 256) * 16, a_ + (tid + 256) * 16); \
        cp16(dA + (tid + 384) * 16, a_ + (tid + 384) * 16); \
        cp16(dB + tid * 16,         b_ + tid * 16); \
        cp16(dB + (tid + 128) * 16, b_ + (tid + 128) * 16); \
        cp16(dB + (tid + 256) * 16, b_ + (tid + 256) * 16); \
        cp16(dB + (tid + 384) * 16, b_ + (tid + 384) * 16); \
        cp_commit(); \
    } while (0)

    ISSUE(0, 0);
    ISSUE(1, 1);

    int stage = 0;
    for (int i = 0; i < NCHUNK; i++) {
        if (i < NCHUNK - 1) cp_wait1(); else cp_wait0();
        __syncthreads();
        if (i + 2 < NCHUNK) {
            int ns = stage + 2; if (ns >= 3) ns -= 3;   // holds chunk i-1: consumed
            ISSUE(i + 2, ns);
        }

        const uint32_t aBase = sb + stage * 16384;
        const uint32_t bBase = aBase + 8192;
        #pragma unroll
        for (int ks = 0; ks < 2; ks++) {
            uint32_t a[4][4], b[8][2];
            #pragma unroll
            for (int m8 = 0; m8 < 4; m8++) {
                uint32_t ad = aBase + (((wm * 4 + m8) * 2 + ks) * 32 + lane) * 16;
                asm volatile("ld.shared.v4.b32 {%0,%1,%2,%3}, [%4];"
                    : "=r"(a[m8][0]), "=r"(a[m8][1]), "=r"(a[m8][2]), "=r"(a[m8][3])
                    : "r"(ad));
            }
            #pragma unroll
            for (int n8 = 0; n8 < 8; n8++) {
                uint32_t bd = bBase + (((wn * 8 + n8) * 2 + ks) * 32 + lane) * 8;
                asm volatile("ld.shared.v2.b32 {%0,%1}, [%2];"
                    : "=r"(b[n8][0]), "=r"(b[n8][1]) : "r"(bd));
            }
            #pragma unroll
            for (int m8 = 0; m8 < 4; m8++)
                #pragma unroll
                for (int n8 = 0; n8 < 8; n8++)
                    asm volatile(
                        "mma.sync.aligned.m16n8k16.row.col.f32.f16.f16.f32 "
                        "{%0,%1,%2,%3}, {%4,%5,%6,%7}, {%8,%9}, {%0,%1,%2,%3};"
                        : "+f"(acc[m8][n8][0]), "+f"(acc[m8][n8][1]),
                          "+f"(acc[m8][n8][2]), "+f"(acc[m8][n8][3])
                        : "r"(a[m8][0]), "r"(a[m8][1]), "r"(a[m8][2]), "r"(a[m8][3]),
                          "r"(b[n8][0]), "r"(b[n8][1]));
        }
        stage++; if (stage >= 3) stage = 0;
    }
    #undef ISSUE

    // ---- fused epilogue ----
    float2 biasv[8];
    int ncol[8];
    #pragma unroll
    for (int n8 = 0; n8 < 8; n8++) {
        const int n = nb * 128 + (wn * 8 + n8) * 8 + 2 * qid;
        ncol[n8] = n;
        biasv[n8] = *reinterpret_cast<const float2*>(sub_b + n);
    }

    const int mbase = mt * 128 + wm * 64;
    #pragma unroll
    for (int m8 = 0; m8 < 4; m8++) {
        #pragma unroll
        for (int rh = 0; rh < 2; rh++) {
            const int m  = mbase + m8 * 16 + grp + rh * 8;
            const int b_ = m >> 13;
            const int l  = m & (LL - 1);
            float* ob = out_xup + ((size_t)b_ * (LL * UP) + (size_t)l * UP) * OUTC;
            const float* xr = x + (size_t)m * CC;
            #pragma unroll
            for (int n8 = 0; n8 < 8; n8++) {
                const int n = ncol[n8];
                const int u = n >> 8;
                const int c = n & 255;
                float2 xv = *reinterpret_cast<const float2*>(xr + c);
                float y0 = fmaf(acc[m8][n8][rh * 2 + 0], FC_GAIN, biasv[n8].x);
                float y1 = fmaf(acc[m8][n8][rh * 2 + 1], FC_GAIN, biasv[n8].y);
                float a0 = (y0 >= 0.0f ? y0 : 0.2f * y0) * SQRT2_F;
                float a1 = (y1 >= 0.0f ? y1 : 0.2f * y1) * SQRT2_F;
                float2 ov;
                ov.x = (xv.x + a0) * INV_SQRT2_F;
                ov.y = (xv.y + a1) * INV_SQRT2_F;
                *reinterpret_cast<float2*>(ob + (size_t)u * OUTC + c) = ov;
            }
        }
    }
}

// ---------------------------------------------------------------------------
extern "C" void kernel_launch(void* const* d_in, const int* in_sizes, int n_in,
                              void* d_out, int out_size)
{
    const float* x       = (const float*)d_in[0];
    const float* pc      = (const float*)d_in[1];
    const float* lff_w   = (const float*)d_in[2];
    const float* lff_b   = (const float*)d_in[3];
    const float* cpe_tab = (const float*)d_in[4];
    const float* sub_w   = (const float*)d_in[5];
    const float* sub_b   = (const float*)d_in[6];

    float* out_xup = (float*)d_out;
    float* out_pc  = (float*)d_out + (size_t)MM * UP * OUTC;

    t_prep<<<(3 * RR * PEC + 255) / 256, 256>>>(cpe_tab);
    pe_prep<<<MM / 16, 128>>>(pc, lff_w, lff_b, out_pc);
    a_prep<<<dim3(8, MTILES), 128>>>(x);
    b_prep<<<dim3(NCHUNK, NBLKS), 128>>>(sub_w);
    gemm_hmma<<<dim3(NBLKS, MTILES), 128>>>(x, sub_b, out_xup);
}

// round 16
// speedup vs baseline: 1.1303x; 1.1303x over previous
#include <cuda_runtime.h>
#include <cuda_fp16.h>
#include <math.h>
#include <stdint.h>

// ---------------- problem constants ----------------
#define BB   8
#define LL   8192
#define CC   256
#define PEC  96
#define RR   90
#define UP   4
#define OUTC 256
#define KK   448
#define NN   1024
#define MM   (BB * LL)       // 65536

#define FC_GAIN      0.04724555912615336f   // 1/sqrt(448)
#define SQRT2_F      1.4142135623730951f
#define INV_SQRT2_F  0.7071067811865476f
#define INV_SQRT3_F  0.5773502691896258f

// ---------------- tiling ----------------
#define NCHUNK  14          // K chunks of 32
#define MTILES  512         // M/128
#define NBLKS   8           // N/128
__device__ uint4 g_Afrag[(size_t)MTILES * NCHUNK * 512];   // ~59 MB
__device__ uint4 g_Bfrag[(size_t)NBLKS * NCHUNK * 512];    // ~0.9 MB

__device__ __forceinline__ uint32_t pkh2(float a, float b) {
    __half2 h = __floats2half2_rn(a, b);
    return *reinterpret_cast<uint32_t*>(&h);
}
__device__ __forceinline__ uint32_t smem_u32(const void* p) {
    uint32_t a;
    asm("{ .reg .u64 t; cvta.to.shared.u64 t, %1; cvt.u32.u64 %0, t; }" : "=r"(a) : "l"(p));
    return a;
}
__device__ __forceinline__ void cp16(uint32_t dst, const void* src) {
    asm volatile("cp.async.cg.shared.global [%0], [%1], 16;" :: "r"(dst), "l"(src) : "memory");
}
__device__ __forceinline__ void cp_commit() { asm volatile("cp.async.commit_group;" ::: "memory"); }
__device__ __forceinline__ void cp_wait1()  { asm volatile("cp.async.wait_group 1;" ::: "memory"); }
__device__ __forceinline__ void cp_wait0()  { asm volatile("cp.async.wait_group 0;" ::: "memory"); }

// ---------------------------------------------------------------------------
// Fused prep kernel: ONE launch covers
//   blocks [0, 4096)      : PE fragments (chunks 8..13) + pc_up   (16 rows each)
//   blocks [4096, 8192)   : x fragments  (chunks 0..7)            (id: mt*8+chunk)
//   blocks [8192, 8304)   : sub_w B fragments                     (id: nb*14+chunk)
// ---------------------------------------------------------------------------
#define PE_BLOCKS  4096
#define A_BLOCKS   4096
#define B_BLOCKS   112
#define PREP_BLOCKS (PE_BLOCKS + A_BLOCKS + B_BLOCKS)

__global__ __launch_bounds__(128) void prep_all(
    const float* __restrict__ x,
    const float* __restrict__ pc,
    const float* __restrict__ lff_w,
    const float* __restrict__ lff_b,
    const float* __restrict__ cpe_tab,   // [3, PEC, RR]
    const float* __restrict__ sub_w,     // [NN, KK]
    float* __restrict__ out_pc)          // [BB, LL*UP, 3]
{
    __shared__ __align__(16) char smem_raw[18432];
    const int bid = blockIdx.x;
    const int t   = threadIdx.x;

    if (bid < PE_BLOCKS) {
        // ================= PE part (round-4-proven scalar gather) =========
        float (*spe)[192] = reinterpret_cast<float(*)[192]>(smem_raw);
        const int m0  = bid * 16;
        const int row = t & 15;
        const int dsl = t >> 4;              // 0..7
        const int gm  = m0 + row;

        const float p0 = pc[gm * 3 + 0];
        const float p1 = pc[gm * 3 + 1];
        const float p2 = pc[gm * 3 + 2];
        const float pcv[3] = {p0, p1, p2};

        #pragma unroll
        for (int jj = 0; jj < 12; jj++) {
            const int d = dsl + 8 * jj;      // 0..95, each once
            float s = fmaf(p0, lff_w[d * 3 + 0],
                      fmaf(p1, lff_w[d * 3 + 1],
                      fmaf(p2, lff_w[d * 3 + 2], lff_b[d])));
            spe[row][d] = __sinf(s);

            float acc = 0.0f;
            #pragma unroll
            for (int ch = 0; ch < 3; ch++) {
                float ix  = ((pcv[ch] + 1.0f) * (float)RR - 1.0f) * 0.5f;
                float fi0 = floorf(ix);
                float w   = ix - fi0;
                int   i0  = (int)fi0;
                int   i1  = i0 + 1;
                const float* tr = cpe_tab + ((size_t)ch * PEC + d) * RR;
                float v0 = (i0 >= 0 && i0 < RR) ? tr[i0] : 0.0f;
                float v1 = (i1 >= 0 && i1 < RR) ? tr[i1] : 0.0f;
                acc += v0 * (1.0f - w) + v1 * w;
            }
            spe[row][PEC + d] = acc * INV_SQRT3_F;
        }

        // pc_up: 12 values per row; dsl 0..5 write two each
        if (dsl < 6) {
            #pragma unroll
            for (int q = 0; q < 2; q++) {
                int it = dsl * 2 + q;        // 0..11 = u*3 + k
                int u  = it / 3;
                int k  = it - u * 3;
                float v = (k == 0) ? p0 : (k == 1) ? p1 : p2;
                out_pc[((size_t)gm * UP + u) * 3 + k] = v;
            }
        }
        __syncthreads();

        // fragment writes for chunks 8..13
        const int mt  = m0 >> 7;
        const int m16 = (m0 & 127) >> 4;
        #pragma unroll
        for (int j = 0; j < 3; j++) {
            const int fid  = j * 128 + t;    // 0..383
            const int lane = fid & 31;
            const int ks   = (fid >> 5) & 1;
            const int ch   = fid >> 6;       // 0..5
            const int grp  = lane >> 2;
            const int qid  = lane & 3;
            const int c0   = ch * 32 + ks * 16 + 2 * qid;
            uint4 o;
            o.x = pkh2(spe[grp][c0],     spe[grp][c0 + 1]);
            o.y = pkh2(spe[grp + 8][c0], spe[grp + 8][c0 + 1]);
            o.z = pkh2(spe[grp][c0 + 8], spe[grp][c0 + 9]);
            o.w = pkh2(spe[grp + 8][c0 + 8], spe[grp + 8][c0 + 9]);
            const int chunk = 8 + ch;
            g_Afrag[((size_t)mt * NCHUNK + chunk) * 512 + (m16 * 2 + ks) * 32 + lane] = o;
        }
    } else if (bid < PE_BLOCKS + A_BLOCKS) {
        // ================= A part: x -> fragments chunks 0..7 =============
        float (*s)[36] = reinterpret_cast<float(*)[36]>(smem_raw);
        const int id    = bid - PE_BLOCKS;   // 0..4095
        const int chunk = id & 7;            // 0..7
        const int mt    = id >> 3;           // 0..511
        const int m0    = mt * 128;
        const int k0    = chunk * 32;

        #pragma unroll
        for (int j = 0; j < 8; j++) {
            const int idd = j * 128 + t;
            const int row = idd >> 3;
            const int c4  = (idd & 7) * 4;
            float4 v = *reinterpret_cast<const float4*>(
                x + (size_t)(m0 + row) * CC + k0 + c4);
            *reinterpret_cast<float4*>(&s[row][c4]) = v;
        }
        __syncthreads();

        #pragma unroll
        for (int j = 0; j < 4; j++) {
            const int fid  = j * 128 + t;
            const int lane = fid & 31;
            const int ks   = (fid >> 5) & 1;
            const int m16  = fid >> 6;
            const int grp  = lane >> 2;
            const int qid  = lane & 3;
            const int r0   = m16 * 16 + grp;
            const int c0   = ks * 16 + 2 * qid;
            uint4 o;
            o.x = pkh2(s[r0][c0],     s[r0][c0 + 1]);
            o.y = pkh2(s[r0 + 8][c0], s[r0 + 8][c0 + 1]);
            o.z = pkh2(s[r0][c0 + 8], s[r0][c0 + 9]);
            o.w = pkh2(s[r0 + 8][c0 + 8], s[r0 + 8][c0 + 9]);
            g_Afrag[((size_t)mt * NCHUNK + chunk) * 512 + fid] = o;
        }
    } else {
        // ================= B part: sub_w -> fragments =====================
        const int id    = bid - PE_BLOCKS - A_BLOCKS;  // 0..111
        const int chunk = id % NCHUNK;                 // 0..13
        const int nb    = id / NCHUNK;                 // 0..7
        uint2* dst = reinterpret_cast<uint2*>(g_Bfrag + ((size_t)nb * NCHUNK + chunk) * 512);

        #pragma unroll
        for (int j = 0; j < 8; j++) {
            const int fid  = j * 128 + t;
            const int lane = fid & 31;
            const int ks   = (fid >> 5) & 1;
            const int n8   = fid >> 6;
            const int grp  = lane >> 2;
            const int qid  = lane & 3;
            const int n    = nb * 128 + n8 * 8 + grp;
            const int k    = chunk * 32 + ks * 16 + 2 * qid;
            float2 v01 = *reinterpret_cast<const float2*>(sub_w + (size_t)n * KK + k);
            float2 v23 = *reinterpret_cast<const float2*>(sub_w + (size_t)n * KK + k + 8);
            uint2 o;
            o.x = pkh2(v01.x, v01.y);
            o.y = pkh2(v23.x, v23.y);
            dst[fid] = o;
        }
    }
}

// ---------------------------------------------------------------------------
// GEMM: exact round-4 config (measured 200us, at legacy HMMA roofline).
// fp16 mma.sync m16n8k16, CTA 128x128, BK=32, 3-stage cp.async, distance 2.
// 8 warps: wm in {0,1} (64 rows), wn in {0..3} (32 cols). 2 CTA/SM.
// ---------------------------------------------------------------------------
__global__ __launch_bounds__(256, 2) void gemm_hmma(
    const float* __restrict__ x,
    const float* __restrict__ sub_b,
    float* __restrict__ out_xup)
{
    __shared__ __align__(16) char smem[49152];   // 3 stages x (A 8KB + B 8KB)
    const uint32_t sb = smem_u32(smem);

    const int tid  = threadIdx.x;
    const int wid  = tid >> 5;
    const int lane = tid & 31;
    const int grp  = lane >> 2;
    const int qid  = lane & 3;
    const int wm   = wid >> 2;
    const int wn   = wid & 3;
    const int nb   = blockIdx.x;     // 0..7
    const int mt   = blockIdx.y;     // 0..511

    const char* gA = (const char*)(g_Afrag + (size_t)mt * NCHUNK * 512);
    const char* gB = (const char*)(g_Bfrag + (size_t)nb * NCHUNK * 512);

    float acc[4][4][4];
    #pragma unroll
    for (int i = 0; i < 4; i++)
        #pragma unroll
        for (int j = 0; j < 4; j++)
            #pragma unroll
            for (int q = 0; q < 4; q++) acc[i][j][q] = 0.0f;

    #define ISSUE(c, s) do { \
        const char* a_ = gA + (size_t)(c) * 8192; \
        const char* b_ = gB + (size_t)(c) * 8192; \
        uint32_t dA = sb + (s) * 16384; \
        uint32_t dB = dA + 8192; \
        cp16(dA + tid * 16,         a_ + tid * 16); \
        cp16(dA + (tid + 256) * 16, a_ + (tid + 256) * 16); \
        cp16(dB + tid * 16,         b_ + tid * 16); \
        cp16(dB + (tid + 256) * 16, b_ + (tid + 256) * 16); \
        cp_commit(); \
    } while (0)

    ISSUE(0, 0);
    ISSUE(1, 1);

    int stage = 0;
    for (int i = 0; i < NCHUNK; i++) {
        if (i < NCHUNK - 1) cp_wait1(); else cp_wait0();
        __syncthreads();
        if (i + 2 < NCHUNK) {
            int ns = stage + 2; if (ns >= 3) ns -= 3;   // holds chunk i-1: consumed
            ISSUE(i + 2, ns);
        }

        const uint32_t aBase = sb + stage * 16384;
        const uint32_t bBase = aBase + 8192;
        #pragma unroll
        for (int ks = 0; ks < 2; ks++) {
            uint32_t a[4][4], b[4][2];
            #pragma unroll
            for (int m8 = 0; m8 < 4; m8++) {
                uint32_t ad = aBase + (((wm * 4 + m8) * 2 + ks) * 32 + lane) * 16;
                asm volatile("ld.shared.v4.b32 {%0,%1,%2,%3}, [%4];"
                    : "=r"(a[m8][0]), "=r"(a[m8][1]), "=r"(a[m8][2]), "=r"(a[m8][3])
                    : "r"(ad));
            }
            #pragma unroll
            for (int n8 = 0; n8 < 4; n8++) {
                uint32_t bd = bBase + (((wn * 4 + n8) * 2 + ks) * 32 + lane) * 8;
                asm volatile("ld.shared.v2.b32 {%0,%1}, [%2];"
                    : "=r"(b[n8][0]), "=r"(b[n8][1]) : "r"(bd));
            }
            #pragma unroll
            for (int m8 = 0; m8 < 4; m8++)
                #pragma unroll
                for (int n8 = 0; n8 < 4; n8++)
                    asm volatile(
                        "mma.sync.aligned.m16n8k16.row.col.f32.f16.f16.f32 "
                        "{%0,%1,%2,%3}, {%4,%5,%6,%7}, {%8,%9}, {%0,%1,%2,%3};"
                        : "+f"(acc[m8][n8][0]), "+f"(acc[m8][n8][1]),
                          "+f"(acc[m8][n8][2]), "+f"(acc[m8][n8][3])
                        : "r"(a[m8][0]), "r"(a[m8][1]), "r"(a[m8][2]), "r"(a[m8][3]),
                          "r"(b[n8][0]), "r"(b[n8][1]));
        }
        stage++; if (stage >= 3) stage = 0;
    }
    #undef ISSUE

    // ---- fused epilogue ----
    float2 biasv[4];
    int ncol[4];
    #pragma unroll
    for (int n8 = 0; n8 < 4; n8++) {
        const int n = nb * 128 + wn * 32 + n8 * 8 + 2 * qid;
        ncol[n8] = n;
        biasv[n8] = *reinterpret_cast<const float2*>(sub_b + n);
    }

    const int mbase = mt * 128 + wm * 64;
    #pragma unroll
    for (int m8 = 0; m8 < 4; m8++) {
        #pragma unroll
        for (int rh = 0; rh < 2; rh++) {
            const int m  = mbase + m8 * 16 + grp + rh * 8;
            const int b_ = m >> 13;
            const int l  = m & (LL - 1);
            float* ob = out_xup + ((size_t)b_ * (LL * UP) + (size_t)l * UP) * OUTC;
            const float* xr = x + (size_t)m * CC;
            #pragma unroll
            for (int n8 = 0; n8 < 4; n8++) {
                const int n = ncol[n8];
                const int u = n >> 8;
                const int c = n & 255;
                float2 xv = *reinterpret_cast<const float2*>(xr + c);
                float y0 = fmaf(acc[m8][n8][rh * 2 + 0], FC_GAIN, biasv[n8].x);
                float y1 = fmaf(acc[m8][n8][rh * 2 + 1], FC_GAIN, biasv[n8].y);
                float a0 = (y0 >= 0.0f ? y0 : 0.2f * y0) * SQRT2_F;
                float a1 = (y1 >= 0.0f ? y1 : 0.2f * y1) * SQRT2_F;
                float2 ov;
                ov.x = (xv.x + a0) * INV_SQRT2_F;
                ov.y = (xv.y + a1) * INV_SQRT2_F;
                *reinterpret_cast<float2*>(ob + (size_t)u * OUTC + c) = ov;
            }
        }
    }
}

// ---------------------------------------------------------------------------
extern "C" void kernel_launch(void* const* d_in, const int* in_sizes, int n_in,
                              void* d_out, int out_size)
{
    const float* x       = (const float*)d_in[0];
    const float* pc      = (const float*)d_in[1];
    const float* lff_w   = (const float*)d_in[2];
    const float* lff_b   = (const float*)d_in[3];
    const float* cpe_tab = (const float*)d_in[4];
    const float* sub_w   = (const float*)d_in[5];
    const float* sub_b   = (const float*)d_in[6];

    float* out_xup = (float*)d_out;
    float* out_pc  = (float*)d_out + (size_t)MM * UP * OUTC;

    prep_all<<<PREP_BLOCKS, 128>>>(x, pc, lff_w, lff_b, cpe_tab, sub_w, out_pc);
    gemm_hmma<<<dim3(NBLKS, MTILES), 256>>>(x, sub_b, out_xup);
}